// round 8
// baseline (speedup 1.0000x reference)
#include <cuda_runtime.h>
#include <cuda_fp16.h>

// V=100000, K=32, F=64.
// out[v, 0:64]   = mean over K neighbours of x[idxs[v,k], :]
// out[v, 64:128] = max  over K neighbours
//
// Single persistent kernel, two phases separated by a device-wide barrier:
//   phase 1: convert x fp32 -> fp16 scratch (row = 128B = one cache line)
//   phase 2: warp-per-vertex gather (grid-stride), one LDG.32 per gathered
//            row per warp (exactly one cache line), HADD2/HMAX2 accumulate.
// The gather is at the LTS-bandwidth floor (~33us for 410MB); fusing removes
// the second kernel launch + inter-kernel gap (~1.5us of the previous total).
//
// Barrier: monotonic ticket counter -- replay-safe under CUDA-graph timing
// (each pass adds exactly gridDim.x arrivals; no reset needed). Grid is
// sized to one resident wave (148 SMs x 6 CTAs, enforced by
// __launch_bounds__(256, 6)), so the spin cannot deadlock.

#define KNN  32
#define FDIM 64
#define VMAX 100000
#define GRID_CTAS (148 * 6)

__device__ __align__(16) __half2 g_xh[VMAX * (FDIM / 2)];   // 12.8 MB
__device__ unsigned long long g_bar = 0;                     // ticket counter

__global__ __launch_bounds__(256, 6)
void knn_fused_kernel(const float4* __restrict__ x4,
                      const int*    __restrict__ idxs,
                      float2*       __restrict__ out2,
                      int n8, int V)
{
    // ---------------- phase 1: fp32 -> fp16 convert (grid-stride) ---------
    {
        const int stride = gridDim.x * blockDim.x;
        for (int i = blockIdx.x * blockDim.x + threadIdx.x; i < n8; i += stride) {
            float4 a = x4[2 * i];
            float4 b = x4[2 * i + 1];
            __half2 h0 = __floats2half2_rn(a.x, a.y);
            __half2 h1 = __floats2half2_rn(a.z, a.w);
            __half2 h2 = __floats2half2_rn(b.x, b.y);
            __half2 h3 = __floats2half2_rn(b.z, b.w);
            int4 packed;
            packed.x = *(const int*)&h0;
            packed.y = *(const int*)&h1;
            packed.z = *(const int*)&h2;
            packed.w = *(const int*)&h3;
            *reinterpret_cast<int4*>(&g_xh[4 * i]) = packed;
        }
    }

    // ---------------- device-wide barrier (replay-safe ticket) ------------
    __threadfence();              // make this thread's g_xh stores visible
    __syncthreads();              // all block stores done before arrive
    if (threadIdx.x == 0) {
        const unsigned long long grid = gridDim.x;
        unsigned long long ticket = atomicAdd(&g_bar, 1ULL);
        unsigned long long target = (ticket / grid + 1ULL) * grid;
        while (atomicAdd(&g_bar, 0ULL) < target) {
            __nanosleep(64);
        }
    }
    __syncthreads();
    __threadfence();              // acquire: order gather reads after barrier

    // ---------------- phase 2: gather mean/max (grid-stride, warp/vertex) -
    const int lane   = threadIdx.x & 31;
    const int warp0  = (blockIdx.x * blockDim.x + threadIdx.x) >> 5;
    const int wstride = (gridDim.x * blockDim.x) >> 5;

    // Lane l reads half2 l of each gathered row (row = 32 half2 = 128B).
    const __half2* __restrict__ xl = g_xh + lane;

    for (int v = warp0; v < V; v += wstride) {
        // Coalesced index load: lane l holds idxs[v][l]
        const int my_idx = idxs[v * KNN + lane];

        const __half2 zero = __float2half2_rn(0.0f);
        const __half2 ninf = __float2half2_rn(-65504.0f);
        __half2 sa = zero, sb = zero;      // two 16-deep fp16 sum chains
        __half2 m  = ninf;

        #pragma unroll
        for (int k = 0; k < KNN; ++k) {
            const int idx = __shfl_sync(0xffffffffu, my_idx, k);
            const __half2 h = __ldg(xl + (size_t)(unsigned)idx * (FDIM / 2));
            if (k & 1) sb = __hadd2(sb, h);
            else       sa = __hadd2(sa, h);
            m = __hmax2(m, h);
        }

        const float2 fa = __half22float2(sa);
        const float2 fb = __half22float2(sb);
        const float2 fm = __half22float2(m);
        const float inv = 1.0f / KNN;

        // out row = 128 floats = 64 float2: [mean 32 | max 32] float2.
        out2[v * FDIM + lane]      = make_float2((fa.x + fb.x) * inv,
                                                 (fa.y + fb.y) * inv);
        out2[v * FDIM + 32 + lane] = make_float2(fm.x, fm.y);
    }
}

extern "C" void kernel_launch(void* const* d_in, const int* in_sizes, int n_in,
                              void* d_out, int out_size)
{
    const float4* x4   = (const float4*)d_in[0];  // x: [V, 64] float32
    const int*    idxs = (const int*)d_in[1];     // idxs: [V, 32] int32
    float2*       out2 = (float2*)d_out;          // out: [V, 128] float32

    const int V  = in_sizes[0] / FDIM;            // 100000
    const int n8 = in_sizes[0] / 8;               // V*F/8 (16B per thread)

    knn_fused_kernel<<<GRID_CTAS, 256>>>(x4, idxs, out2, n8, V);
}

// round 9
// speedup vs baseline: 1.2078x; 1.2078x over previous
#include <cuda_runtime.h>
#include <cuda_fp16.h>

// V=100000, K=32, F=64.
// out[v, 0:64]   = mean over K neighbours of x[idxs[v,k], :]
// out[v, 64:128] = max  over K neighbours
//
// Two kernels + PDL:
//   convert: x fp32 -> fp16 scratch (row = 128B); fires
//            griddepcontrol.launch_dependents after its store so gather CTAs
//            launch into SMs as convert CTAs drain.
//   gather:  warp per vertex. Prologue (coalesced idx load, 12.8MB) runs
//            before griddepcontrol.wait -> overlaps convert tail; then the
//            L2-sector-bound gather (3.2M rows x 128B = the ~33us floor).
// R7's PDL attempt lost to collateral (regs 40, occ 63%); fixed here with
// __launch_bounds__(256, 8) (pins 32-reg budget) and a single unconditional
// wait (no divergent wait paths).

#define KNN  32
#define FDIM 64
#define VMAX 100000

__device__ __align__(16) __half2 g_xh[VMAX * (FDIM / 2)];   // 12.8 MB

__global__ __launch_bounds__(256)
void convert_kernel(const float4* __restrict__ x4, int n8)   // n8 = V*F/8
{
    int i = blockIdx.x * blockDim.x + threadIdx.x;
    if (i < n8) {
        float4 a = x4[2 * i];
        float4 b = x4[2 * i + 1];
        __half2 h0 = __floats2half2_rn(a.x, a.y);
        __half2 h1 = __floats2half2_rn(a.z, a.w);
        __half2 h2 = __floats2half2_rn(b.x, b.y);
        __half2 h3 = __floats2half2_rn(b.z, b.w);
        int4 packed;
        packed.x = *(const int*)&h0;
        packed.y = *(const int*)&h1;
        packed.z = *(const int*)&h2;
        packed.w = *(const int*)&h3;
        *reinterpret_cast<int4*>(&g_xh[4 * i]) = packed;
    }
    // Work done: allow dependent gather CTAs to start launching.
    asm volatile("griddepcontrol.launch_dependents;" ::: "memory");
}

__global__ __launch_bounds__(256, 8)   // pin 32-reg budget -> full occupancy
void knn_mean_max_kernel(const int* __restrict__ idxs,
                         float2*    __restrict__ out2,
                         int V)
{
    const int warp = (blockIdx.x * blockDim.x + threadIdx.x) >> 5;
    const int lane = threadIdx.x & 31;
    const bool active = (warp < V);

    // Prologue independent of convert's output: coalesced index load.
    int my_idx = 0;
    if (active) my_idx = idxs[warp * KNN + lane];

    // Single unconditional wait: blocks until convert's g_xh writes are
    // visible (primary grid complete).
    asm volatile("griddepcontrol.wait;" ::: "memory");

    if (!active) return;

    const __half2 zero = __float2half2_rn(0.0f);
    const __half2 ninf = __float2half2_rn(-65504.0f);
    __half2 sa = zero, sb = zero;      // two 16-deep fp16 sum chains
    __half2 m  = ninf;

    // Lane l reads half2 l of each gathered row (row = 32 half2 = 128B):
    // one LDG.32 per row per warp -> exactly one cache line per instruction.
    const __half2* __restrict__ xl = g_xh + lane;

    #pragma unroll
    for (int k = 0; k < KNN; ++k) {
        const int idx = __shfl_sync(0xffffffffu, my_idx, k);
        const __half2 h = __ldg(xl + (size_t)(unsigned)idx * (FDIM / 2));
        if (k & 1) sb = __hadd2(sb, h);
        else       sa = __hadd2(sa, h);
        m = __hmax2(m, h);
    }

    const float2 fa = __half22float2(sa);
    const float2 fb = __half22float2(sb);
    const float2 fm = __half22float2(m);
    const float inv = 1.0f / KNN;

    // out row = 128 floats = 64 float2: [mean 32 float2 | max 32 float2].
    out2[warp * FDIM + lane]      = make_float2((fa.x + fb.x) * inv,
                                                (fa.y + fb.y) * inv);
    out2[warp * FDIM + 32 + lane] = make_float2(fm.x, fm.y);
}

extern "C" void kernel_launch(void* const* d_in, const int* in_sizes, int n_in,
                              void* d_out, int out_size)
{
    const float4* x4   = (const float4*)d_in[0];  // x: [V, 64] float32
    const int*    idxs = (const int*)d_in[1];     // idxs: [V, 32] int32
    float2*       out2 = (float2*)d_out;          // out: [V, 128] float32

    const int V  = in_sizes[0] / FDIM;            // 100000
    const int n8 = in_sizes[0] / 8;               // V*F/8 (16B per thread)

    convert_kernel<<<(n8 + 255) / 256, 256>>>(x4, n8);

    const int warps_per_block = 256 / 32;         // 8
    const int blocks = (V + warps_per_block - 1) / warps_per_block;

    cudaLaunchConfig_t cfg = {};
    cfg.gridDim  = dim3((unsigned)blocks, 1, 1);
    cfg.blockDim = dim3(256, 1, 1);
    cfg.dynamicSmemBytes = 0;
    cfg.stream = 0;

    cudaLaunchAttribute attrs[1];
    attrs[0].id = cudaLaunchAttributeProgrammaticStreamSerialization;
    attrs[0].val.programmaticStreamSerializationAllowed = 1;
    cfg.attrs = attrs;
    cfg.numAttrs = 1;

    cudaLaunchKernelEx(&cfg, knn_mean_max_kernel, idxs, out2, V);
}